// round 9
// baseline (speedup 1.0000x reference)
#include <cuda_runtime.h>
#include <cuda_fp16.h>
#include <cstdint>

#define M_DIM 16384
#define N_DIM 4096
#define K_DIM 1024
#define TOPK  409

// ---------------------------------------------------------------------------
// Device scratch
// ---------------------------------------------------------------------------
__device__ int    g_has_neg;
__device__ float  g_S[N_DIM];                                // row sums of W
__device__ __half g_xh[(size_t)M_DIM * K_DIM];               // fp16 x
__device__ __half g_wh[(size_t)N_DIM * K_DIM];               // fp16 W

// ---------------------------------------------------------------------------
// K1: flag init
// ---------------------------------------------------------------------------
__global__ void init_flags_kernel() { g_has_neg = 0; }

// ---------------------------------------------------------------------------
// K2: fused fp32->fp16 conversion of x + negative scan
// ---------------------------------------------------------------------------
__global__ void __launch_bounds__(256)
conv_x_scan_kernel(const float4* __restrict__ src) {
    uint2* dst = (uint2*)g_xh;
    const int n4 = (M_DIM * K_DIM) / 4;
    bool neg = false;
    for (int i = blockIdx.x * blockDim.x + threadIdx.x; i < n4;
         i += gridDim.x * blockDim.x) {
        float4 v = src[i];
        neg |= (v.x < 0.f) | (v.y < 0.f) | (v.z < 0.f) | (v.w < 0.f);
        __half2 h01 = __floats2half2_rn(v.x, v.y);
        __half2 h23 = __floats2half2_rn(v.z, v.w);
        uint2 u;
        u.x = *(uint32_t*)&h01;
        u.y = *(uint32_t*)&h23;
        dst[i] = u;
    }
    if (__any_sync(0xFFFFFFFFu, neg) && (threadIdx.x & 31) == 0)
        g_has_neg = 1;
}

// ---------------------------------------------------------------------------
// K3: fused fp32->fp16 conversion of W + per-row sums. One block per W row.
// ---------------------------------------------------------------------------
__global__ void __launch_bounds__(256)
conv_w_rowsum_kernel(const float4* __restrict__ src) {
    __shared__ float ws[8];
    const int row = blockIdx.x;
    const int tid = threadIdx.x;
    const float4* s = src + (size_t)row * (K_DIM / 4);
    uint2* d = (uint2*)(g_wh + (size_t)row * K_DIM);

    float4 v = s[tid];
    float sum = v.x + v.y + v.z + v.w;
    __half2 h01 = __floats2half2_rn(v.x, v.y);
    __half2 h23 = __floats2half2_rn(v.z, v.w);
    uint2 u;
    u.x = *(uint32_t*)&h01;
    u.y = *(uint32_t*)&h23;
    d[tid] = u;

#pragma unroll
    for (int off = 16; off >= 1; off >>= 1)
        sum += __shfl_xor_sync(0xFFFFFFFFu, sum, off);
    if ((tid & 31) == 0) ws[tid >> 5] = sum;
    __syncthreads();
    if (tid == 0) {
        float t = 0.f;
#pragma unroll
        for (int w = 0; w < 8; w++) t += ws[w];
        g_S[row] = t;
    }
}

// ---------------------------------------------------------------------------
// K4: fp16 mma.sync GEMM  P[M,N] = xh[M,K] * wh[N,K]^T   (fp32 accumulate)
// 128x128 CTA tile, BK=64 halves, 3-stage cp.async, ONE sync per chunk.
// ---------------------------------------------------------------------------
#define BKH 64
#define ROWB 144
#define NSTAGES 3
#define GCHUNKS (K_DIM / BKH)          // 16
#define ATILE_B (128 * ROWB)           // 18432
#define STAGE_B (2 * ATILE_B)          // 36864

#define CPA16(dst, src) \
    asm volatile("cp.async.cg.shared.global [%0], [%1], 16;" :: "r"(dst), "l"(src) : "memory")
#define CPA_COMMIT() asm volatile("cp.async.commit_group;" ::: "memory")
#define CPA_WAIT1()  asm volatile("cp.async.wait_group 1;" ::: "memory")

__device__ __forceinline__ uint32_t smem_u32(const void* p) {
    uint32_t a;
    asm("{ .reg .u64 t; cvta.to.shared.u64 t, %1; cvt.u32.u64 %0, t; }"
        : "=r"(a) : "l"(p));
    return a;
}

__device__ __forceinline__ void ldmx4(uint32_t r[4], uint32_t addr) {
    asm volatile("ldmatrix.sync.aligned.m8n8.x4.shared.b16 {%0,%1,%2,%3}, [%4];"
                 : "=r"(r[0]), "=r"(r[1]), "=r"(r[2]), "=r"(r[3]) : "r"(addr));
}

__device__ __forceinline__ void mma_f16(float c[4], const uint32_t a[4],
                                        const uint32_t b0, const uint32_t b1) {
    asm volatile(
        "mma.sync.aligned.m16n8k16.row.col.f32.f16.f16.f32 "
        "{%0,%1,%2,%3}, {%4,%5,%6,%7}, {%8,%9}, {%0,%1,%2,%3};"
        : "+f"(c[0]), "+f"(c[1]), "+f"(c[2]), "+f"(c[3])
        : "r"(a[0]), "r"(a[1]), "r"(a[2]), "r"(a[3]), "r"(b0), "r"(b1));
}

__global__ void __launch_bounds__(256, 2)
gemm_f16_kernel(float* __restrict__ C) {
    extern __shared__ char smem[];
    const uint32_t sbase = smem_u32(smem);

    const int tid  = threadIdx.x;
    const int wid  = tid >> 5;
    const int lane = tid & 31;
    const int g = lane >> 2;
    const int t = lane & 3;
    const int bm = blockIdx.y * 128;
    const int bn = blockIdx.x * 128;

    const int warp_m = (wid & 1) * 64;
    const int warp_n = (wid >> 1) * 32;

    const __half* Agbase = g_xh + (size_t)bm * K_DIM;
    const __half* Bgbase = g_wh + (size_t)bn * K_DIM;

    const int j8   = lane & 7;
    const int quad = lane >> 3;
    const int arow  = warp_m + ((quad & 1) << 3) + j8;
    const int akoff = (quad & 2) ? 16 : 0;
    const int brow  = warp_n + ((quad & 2) << 2) + j8;
    const int bkoff = (quad & 1) ? 16 : 0;

    uint32_t aoff[4], boff[2];
#pragma unroll
    for (int i = 0; i < 4; i++) aoff[i] = (uint32_t)((arow + i * 16) * ROWB + akoff);
#pragma unroll
    for (int jt = 0; jt < 2; jt++) boff[jt] = (uint32_t)((brow + jt * 16) * ROWB + bkoff);

    float acc[4][4][4];
#pragma unroll
    for (int i = 0; i < 4; i++)
#pragma unroll
        for (int j = 0; j < 4; j++)
#pragma unroll
            for (int q = 0; q < 4; q++) acc[i][j][q] = 0.f;

    const int lrow  = tid >> 1;          // 0..127
    const int lc0   = (tid & 1) * 4;     // 16B-segment base (0 or 4)

    auto issue = [&](int c, int s) {
        const uint32_t stA = sbase + s * STAGE_B;
        const uint32_t stB = stA + ATILE_B;
#pragma unroll
        for (int q = 0; q < 4; q++) {
            const int c16 = lc0 + q;     // 0..7
            const uint32_t doff = (uint32_t)(lrow * ROWB + c16 * 16);
            CPA16(stA + doff, Agbase + (size_t)lrow * K_DIM + c * BKH + c16 * 8);
            CPA16(stB + doff, Bgbase + (size_t)lrow * K_DIM + c * BKH + c16 * 8);
        }
    };

    issue(0, 0); CPA_COMMIT();
    issue(1, 1); CPA_COMMIT();

    for (int c = 0; c < GCHUNKS; ++c) {
        CPA_WAIT1();
        __syncthreads();

        const int cn = c + 2;
        if (cn < GCHUNKS) issue(cn, cn % NSTAGES);
        CPA_COMMIT();

        const uint32_t stA = sbase + (c % NSTAGES) * STAGE_B;
        const uint32_t stB = stA + ATILE_B;

#pragma unroll
        for (int ks = 0; ks < 4; ++ks) {
            uint32_t a[4][4], b[2][4];
#pragma unroll
            for (int i = 0; i < 4; i++)
                ldmx4(a[i], stA + aoff[i] + ks * 32);
#pragma unroll
            for (int jt = 0; jt < 2; jt++)
                ldmx4(b[jt], stB + boff[jt] + ks * 32);
#pragma unroll
            for (int i = 0; i < 4; i++) {
                mma_f16(acc[i][0], a[i], b[0][0], b[0][1]);
                mma_f16(acc[i][1], a[i], b[0][2], b[0][3]);
                mma_f16(acc[i][2], a[i], b[1][0], b[1][1]);
                mma_f16(acc[i][3], a[i], b[1][2], b[1][3]);
            }
        }
        // no trailing sync: the next iteration's overwrite of stage (c-1)%3
        // happens only after its own __syncthreads, which proves all warps
        // finished reading that stage in this iteration.
    }

#pragma unroll
    for (int i = 0; i < 4; i++) {
#pragma unroll
        for (int j = 0; j < 4; j++) {
            const int r0 = bm + warp_m + i * 16 + g;
            const int cc = bn + warp_n + j * 8 + 2 * t;
            float2 v0 = {acc[i][j][0], acc[i][j][1]};
            float2 v1 = {acc[i][j][2], acc[i][j][3]};
            *(float2*)(C + (size_t)r0 * N_DIM + cc) = v0;
            *(float2*)(C + (size_t)(r0 + 8) * N_DIM + cc) = v1;
        }
    }
}

// ---------------------------------------------------------------------------
// K5: per-row exact top-K with approximate-GEMM fixup, then normalize.
// 512 threads/block, 2-pass radix + barrier-correct parallel suffix scan.
// ---------------------------------------------------------------------------
__device__ __forceinline__ unsigned float_to_key(float f) {
    unsigned u = __float_as_uint(f);
    return (u & 0x80000000u) ? ~u : (u | 0x80000000u);
}
__device__ __forceinline__ float key_to_float(unsigned k) {
    unsigned u = (k & 0x80000000u) ? (k ^ 0x80000000u) : ~k;
    return __uint_as_float(u);
}

#define CAND_CAP 192
#define MARGIN 0.0075f

__global__ void __launch_bounds__(512)
fixup_kernel(float* __restrict__ P, const float* __restrict__ X,
             const float* __restrict__ Wm, float* __restrict__ out) {
    __shared__ float    s_row[N_DIM];
    __shared__ float    s_xs[K_DIM];
    __shared__ unsigned char s_mask[N_DIM];
    __shared__ unsigned hist[256];
    __shared__ unsigned s_wtot[8];
    __shared__ unsigned s_woff[8];
    __shared__ unsigned s_prefix, s_rem;
    __shared__ int      s_cnt, s_nc;
    __shared__ int      s_cidx[CAND_CAP];
    __shared__ float    s_cval[CAND_CAP];
    __shared__ float    s_wsum[16];
    __shared__ float    s_inv;

    const int row = blockIdx.x;
    const int tid = threadIdx.x;
    const int wid = tid >> 5, lane = tid & 31;
    const bool bip = (g_has_neg == 0);

    const float4* p4 = (const float4*)(P + (size_t)row * N_DIM);

    float v[8];
#pragma unroll
    for (int i = 0; i < 2; i++) {
        float4 f = p4[tid + 512 * i];
        const int cb = (tid + 512 * i) * 4;
        if (bip) {
            f.x = 2.f * f.x - g_S[cb + 0];
            f.y = 2.f * f.y - g_S[cb + 1];
            f.z = 2.f * f.z - g_S[cb + 2];
            f.w = 2.f * f.w - g_S[cb + 3];
        }
        v[i * 4 + 0] = f.x; v[i * 4 + 1] = f.y;
        v[i * 4 + 2] = f.z; v[i * 4 + 3] = f.w;
        s_row[cb + 0] = f.x; s_row[cb + 1] = f.y;
        s_row[cb + 2] = f.z; s_row[cb + 3] = f.w;
    }

    unsigned key[8];
#pragma unroll
    for (int i = 0; i < 8; i++) key[i] = float_to_key(v[i]);

    // load x row concurrently (independent of select)
#pragma unroll
    for (int i = 0; i < 2; i++) {
        const int k = tid + 512 * i;
        float xv = X[(size_t)row * K_DIM + k];
        s_xs[k] = bip ? (xv - 0.5f) * 2.0f : xv;
    }
    if (tid == 0) { s_cnt = 0; s_nc = 0; s_prefix = 0; s_rem = TOPK; }
    if (tid < 256) hist[tid] = 0;
    __syncthreads();

    // ---- 2-pass MSD radix select (top 16 key bits) ----
    unsigned prefix = 0;
    unsigned remaining = TOPK;
#pragma unroll
    for (int pass = 0; pass < 2; pass++) {
        const int shift = pass ? 16 : 24;
#pragma unroll
        for (int i = 0; i < 8; i++) {
            bool part = pass ? ((key[i] & 0xFF000000u) == prefix) : true;
            if (part) atomicAdd(&hist[(key[i] >> shift) & 255u], 1u);
        }
        __syncthreads();

        // phase 1: per-warp inclusive suffix scan (sfx lives in a register
        // across the barriers below)
        unsigned sfx = 0;
        if (tid < 256) {
            sfx = hist[tid];
#pragma unroll
            for (int off = 1; off < 32; off <<= 1) {
                unsigned u = __shfl_down_sync(0xFFFFFFFFu, sfx, off);
                if (lane + off < 32) sfx += u;
            }
            if (lane == 0) s_wtot[wid] = sfx;
        }
        __syncthreads();                       // all s_wtot visible

        // phase 2: warp-total suffix offsets
        if (tid < 8) {
            unsigned t2 = s_wtot[tid];
#pragma unroll
            for (int off = 1; off < 8; off <<= 1) {
                unsigned u = __shfl_down_sync(0xFFu, t2, off);
                if (tid + off < 8) t2 += u;
            }
            s_woff[tid] = t2 - s_wtot[tid];    // sum of warps strictly above
        }
        __syncthreads();                       // s_woff visible

        // phase 3: pick winner bin (suffix crossing)
        if (tid < 256) {
            const unsigned suffix = sfx + s_woff[wid];     // count(bins >= tid)
            unsigned nxt = __shfl_down_sync(0xFFFFFFFFu, suffix, 1);
            if (lane == 31) nxt = s_woff[wid];             // suffix of tid+1
            if (suffix >= remaining && nxt < remaining) {
                s_prefix = prefix | ((unsigned)tid << shift);
                s_rem = remaining - nxt;                   // rank inside bucket
            }
        }
        __syncthreads();
        prefix = s_prefix;
        remaining = s_rem;
        if (tid < 256) hist[tid] = 0;          // clear for next pass
        __syncthreads();
    }

    const float t_lo = key_to_float(prefix);
    const float t_hi = key_to_float(prefix | 0xFFFFu);
    const float hi = t_hi + MARGIN;
    const float lo = t_lo - MARGIN;

    // ---- candidates + sure count ----
    int myin = 0;
#pragma unroll
    for (int i = 0; i < 8; i++) {
        const int col = (tid + 512 * (i >> 2)) * 4 + (i & 3);
        const float val = v[i];
        const bool sure = (val > hi);
        s_mask[col] = sure ? 1 : 0;
        myin += sure ? 1 : 0;
        if (val <= hi && val >= lo) {
            int slot = atomicAdd(&s_nc, 1);
            if (slot < CAND_CAP) s_cidx[slot] = col;
        }
    }
#pragma unroll
    for (int off = 16; off >= 1; off >>= 1)
        myin += __shfl_xor_sync(0xFFFFFFFFu, myin, off);
    if (lane == 0) atomicAdd(&s_cnt, myin);
    __syncthreads();

    const int n_sure = s_cnt;
    const int n_c = min(s_nc, CAND_CAP);
    int need = TOPK - n_sure;
    if (need < 0) need = 0;
    if (need > n_c) need = n_c;

    // ---- exact fp32 dots for candidates (one warp per candidate) ----
    for (int j = wid; j < n_c; j += 16) {
        const int col = s_cidx[j];
        const float* wr = Wm + (size_t)col * K_DIM;
        float accv = 0.f;
#pragma unroll
        for (int i = 0; i < 32; i++) {
            const int k = lane + i * 32;
            accv = fmaf(s_xs[k], wr[k], accv);
        }
#pragma unroll
        for (int off = 16; off >= 1; off >>= 1)
            accv += __shfl_xor_sync(0xFFFFFFFFu, accv, off);
        if (lane == 0) {
            s_cval[j] = accv;
            s_row[col] = accv;
        }
    }
    __syncthreads();

    // ---- exact top-`need` among candidates ----
    if (tid < n_c) {
        const float vt = s_cval[tid];
        int rank = 0;
        for (int k = 0; k < n_c; k++) {
            const float vk = s_cval[k];
            rank += (vk > vt || (vk == vt && k < tid)) ? 1 : 0;
        }
        s_mask[s_cidx[tid]] = (rank < need) ? 1 : 0;
    }
    __syncthreads();

    // ---- encode + L2 normalize ----
    float e[8];
    float ss = 0.f;
#pragma unroll
    for (int i = 0; i < 8; i++) {
        const int col = (tid + 512 * (i >> 2)) * 4 + (i & 3);
        const float val = s_row[col];
        const float ev = s_mask[col] ? fmaxf(val, 0.f) : 0.f;
        e[i] = ev;
        ss = fmaf(ev, ev, ss);
    }
#pragma unroll
    for (int off = 16; off >= 1; off >>= 1)
        ss += __shfl_xor_sync(0xFFFFFFFFu, ss, off);
    if (lane == 0) s_wsum[wid] = ss;
    __syncthreads();
    if (tid == 0) {
        float tt = 0.f;
#pragma unroll
        for (int w = 0; w < 16; w++) tt += s_wsum[w];
        s_inv = 1.0f / fmaxf(sqrtf(tt), 1e-12f);
    }
    __syncthreads();
    const float inv = s_inv;

    float4* o4 = (float4*)(out + (size_t)row * N_DIM);
#pragma unroll
    for (int i = 0; i < 2; i++) {
        float4 f;
        f.x = e[i * 4 + 0] * inv; f.y = e[i * 4 + 1] * inv;
        f.z = e[i * 4 + 2] * inv; f.w = e[i * 4 + 3] * inv;
        o4[tid + 512 * i] = f;
    }
}

// ---------------------------------------------------------------------------
// Launch
// ---------------------------------------------------------------------------
extern "C" void kernel_launch(void* const* d_in, const int* in_sizes, int n_in,
                              void* d_out, int out_size) {
    const float* x = (const float*)d_in[0];   // [16384, 1024]
    const float* w = (const float*)d_in[1];   // [4096, 1024]
    float* out = (float*)d_out;               // [16384, 4096]

    const int smem_bytes = NSTAGES * STAGE_B;
    cudaFuncSetAttribute(gemm_f16_kernel,
                         cudaFuncAttributeMaxDynamicSharedMemorySize, smem_bytes);

    init_flags_kernel<<<1, 1>>>();
    conv_x_scan_kernel<<<2048, 256>>>((const float4*)x);
    conv_w_rowsum_kernel<<<N_DIM, 256>>>((const float4*)w);

    dim3 ggrid(N_DIM / 128, M_DIM / 128);
    gemm_f16_kernel<<<ggrid, 256, smem_bytes>>>(out);

    fixup_kernel<<<M_DIM, 512>>>(out, x, w, out);
}

// round 11
// speedup vs baseline: 1.2246x; 1.2246x over previous
#include <cuda_runtime.h>
#include <cuda_fp16.h>
#include <cstdint>

#define M_DIM 16384
#define N_DIM 4096
#define K_DIM 1024
#define TOPK  409

// ---------------------------------------------------------------------------
// Device scratch
// ---------------------------------------------------------------------------
__device__ int    g_has_neg;
__device__ float  g_S[N_DIM];                                // row sums of W
__device__ __half g_xh[(size_t)M_DIM * K_DIM];               // fp16 x
__device__ __half g_wh[(size_t)N_DIM * K_DIM];               // fp16 W

// ---------------------------------------------------------------------------
// K1: flag init
// ---------------------------------------------------------------------------
__global__ void init_flags_kernel() { g_has_neg = 0; }

// ---------------------------------------------------------------------------
// K2: fused fp32->fp16 conversion of x + negative scan
// ---------------------------------------------------------------------------
__global__ void __launch_bounds__(256)
conv_x_scan_kernel(const float4* __restrict__ src) {
    uint2* dst = (uint2*)g_xh;
    const int n4 = (M_DIM * K_DIM) / 4;
    bool neg = false;
    for (int i = blockIdx.x * blockDim.x + threadIdx.x; i < n4;
         i += gridDim.x * blockDim.x) {
        float4 v = src[i];
        neg |= (v.x < 0.f) | (v.y < 0.f) | (v.z < 0.f) | (v.w < 0.f);
        __half2 h01 = __floats2half2_rn(v.x, v.y);
        __half2 h23 = __floats2half2_rn(v.z, v.w);
        uint2 u;
        u.x = *(uint32_t*)&h01;
        u.y = *(uint32_t*)&h23;
        dst[i] = u;
    }
    if (__any_sync(0xFFFFFFFFu, neg) && (threadIdx.x & 31) == 0)
        g_has_neg = 1;
}

// ---------------------------------------------------------------------------
// K3: fused fp32->fp16 conversion of W + per-row sums. One block per W row.
// ---------------------------------------------------------------------------
__global__ void __launch_bounds__(256)
conv_w_rowsum_kernel(const float4* __restrict__ src) {
    __shared__ float ws[8];
    const int row = blockIdx.x;
    const int tid = threadIdx.x;
    const float4* s = src + (size_t)row * (K_DIM / 4);
    uint2* d = (uint2*)(g_wh + (size_t)row * K_DIM);

    float4 v = s[tid];
    float sum = v.x + v.y + v.z + v.w;
    __half2 h01 = __floats2half2_rn(v.x, v.y);
    __half2 h23 = __floats2half2_rn(v.z, v.w);
    uint2 u;
    u.x = *(uint32_t*)&h01;
    u.y = *(uint32_t*)&h23;
    d[tid] = u;

#pragma unroll
    for (int off = 16; off >= 1; off >>= 1)
        sum += __shfl_xor_sync(0xFFFFFFFFu, sum, off);
    if ((tid & 31) == 0) ws[tid >> 5] = sum;
    __syncthreads();
    if (tid == 0) {
        float t = 0.f;
#pragma unroll
        for (int w = 0; w < 8; w++) t += ws[w];
        g_S[row] = t;
    }
}

// ---------------------------------------------------------------------------
// K4: fp16 mma.sync GEMM  P[M,N] = xh[M,K] * wh[N,K]^T   (fp32 accumulate)
// 128x128 CTA tile, BK=64 halves, 3-stage cp.async, ONE sync per chunk.
// Loader: seg = tid + 256*q -> row = seg>>3, c16 = seg&7 (contiguous 128B
// per 4 rows per warp instruction; full-sector coalescing).
// ---------------------------------------------------------------------------
#define BKH 64
#define ROWB 144
#define NSTAGES 3
#define GCHUNKS (K_DIM / BKH)          // 16
#define ATILE_B (128 * ROWB)           // 18432
#define STAGE_B (2 * ATILE_B)          // 36864

#define CPA16(dst, src) \
    asm volatile("cp.async.cg.shared.global [%0], [%1], 16;" :: "r"(dst), "l"(src) : "memory")
#define CPA_COMMIT() asm volatile("cp.async.commit_group;" ::: "memory")
#define CPA_WAIT1()  asm volatile("cp.async.wait_group 1;" ::: "memory")

__device__ __forceinline__ uint32_t smem_u32(const void* p) {
    uint32_t a;
    asm("{ .reg .u64 t; cvta.to.shared.u64 t, %1; cvt.u32.u64 %0, t; }"
        : "=r"(a) : "l"(p));
    return a;
}

__device__ __forceinline__ void ldmx4(uint32_t r[4], uint32_t addr) {
    asm volatile("ldmatrix.sync.aligned.m8n8.x4.shared.b16 {%0,%1,%2,%3}, [%4];"
                 : "=r"(r[0]), "=r"(r[1]), "=r"(r[2]), "=r"(r[3]) : "r"(addr));
}

__device__ __forceinline__ void mma_f16(float c[4], const uint32_t a[4],
                                        const uint32_t b0, const uint32_t b1) {
    asm volatile(
        "mma.sync.aligned.m16n8k16.row.col.f32.f16.f16.f32 "
        "{%0,%1,%2,%3}, {%4,%5,%6,%7}, {%8,%9}, {%0,%1,%2,%3};"
        : "+f"(c[0]), "+f"(c[1]), "+f"(c[2]), "+f"(c[3])
        : "r"(a[0]), "r"(a[1]), "r"(a[2]), "r"(a[3]), "r"(b0), "r"(b1));
}

__global__ void __launch_bounds__(256, 2)
gemm_f16_kernel(float* __restrict__ C) {
    extern __shared__ char smem[];
    const uint32_t sbase = smem_u32(smem);

    const int tid  = threadIdx.x;
    const int wid  = tid >> 5;
    const int lane = tid & 31;
    const int g = lane >> 2;
    const int t = lane & 3;
    const int bm = blockIdx.y * 128;
    const int bn = blockIdx.x * 128;

    const int warp_m = (wid & 1) * 64;
    const int warp_n = (wid >> 1) * 32;

    const __half* Agbase = g_xh + (size_t)bm * K_DIM;
    const __half* Bgbase = g_wh + (size_t)bn * K_DIM;

    const int j8   = lane & 7;
    const int quad = lane >> 3;
    const int arow  = warp_m + ((quad & 1) << 3) + j8;
    const int akoff = (quad & 2) ? 16 : 0;
    const int brow  = warp_n + ((quad & 2) << 2) + j8;
    const int bkoff = (quad & 1) ? 16 : 0;

    uint32_t aoff[4], boff[2];
#pragma unroll
    for (int i = 0; i < 4; i++) aoff[i] = (uint32_t)((arow + i * 16) * ROWB + akoff);
#pragma unroll
    for (int jt = 0; jt < 2; jt++) boff[jt] = (uint32_t)((brow + jt * 16) * ROWB + bkoff);

    float acc[4][4][4];
#pragma unroll
    for (int i = 0; i < 4; i++)
#pragma unroll
        for (int j = 0; j < 4; j++)
#pragma unroll
            for (int q = 0; q < 4; q++) acc[i][j][q] = 0.f;

    auto issue = [&](int c, int s) {
        const uint32_t stA = sbase + s * STAGE_B;
        const uint32_t stB = stA + ATILE_B;
#pragma unroll
        for (int q = 0; q < 4; q++) {
            const int seg = tid + 256 * q;       // 0..1023
            const int row = seg >> 3;            // 0..127
            const int c16 = seg & 7;             // 0..7
            const uint32_t doff = (uint32_t)(row * ROWB + c16 * 16);
            CPA16(stA + doff, Agbase + (size_t)row * K_DIM + c * BKH + c16 * 8);
            CPA16(stB + doff, Bgbase + (size_t)row * K_DIM + c * BKH + c16 * 8);
        }
    };

    issue(0, 0); CPA_COMMIT();
    issue(1, 1); CPA_COMMIT();

    for (int c = 0; c < GCHUNKS; ++c) {
        CPA_WAIT1();
        __syncthreads();

        const int cn = c + 2;
        if (cn < GCHUNKS) issue(cn, cn % NSTAGES);
        CPA_COMMIT();

        const uint32_t stA = sbase + (c % NSTAGES) * STAGE_B;
        const uint32_t stB = stA + ATILE_B;

#pragma unroll
        for (int ks = 0; ks < 4; ++ks) {
            uint32_t a[4][4], b[2][4];
#pragma unroll
            for (int i = 0; i < 4; i++)
                ldmx4(a[i], stA + aoff[i] + ks * 32);
#pragma unroll
            for (int jt = 0; jt < 2; jt++)
                ldmx4(b[jt], stB + boff[jt] + ks * 32);
#pragma unroll
            for (int i = 0; i < 4; i++) {
                mma_f16(acc[i][0], a[i], b[0][0], b[0][1]);
                mma_f16(acc[i][1], a[i], b[0][2], b[0][3]);
                mma_f16(acc[i][2], a[i], b[1][0], b[1][1]);
                mma_f16(acc[i][3], a[i], b[1][2], b[1][3]);
            }
        }
        // no trailing sync: the next iteration's overwrite of this stage only
        // happens after its own __syncthreads (all reads provably done).
    }

#pragma unroll
    for (int i = 0; i < 4; i++) {
#pragma unroll
        for (int j = 0; j < 4; j++) {
            const int r0 = bm + warp_m + i * 16 + g;
            const int cc = bn + warp_n + j * 8 + 2 * t;
            float2 v0 = {acc[i][j][0], acc[i][j][1]};
            float2 v1 = {acc[i][j][2], acc[i][j][3]};
            *(float2*)(C + (size_t)r0 * N_DIM + cc) = v0;
            *(float2*)(C + (size_t)(r0 + 8) * N_DIM + cc) = v1;
        }
    }
}

// ---------------------------------------------------------------------------
// K5: per-row exact top-K with approximate-GEMM fixup, then normalize.
// 512 threads/block, 2-pass radix + barrier-correct parallel suffix scan.
// ---------------------------------------------------------------------------
__device__ __forceinline__ unsigned float_to_key(float f) {
    unsigned u = __float_as_uint(f);
    return (u & 0x80000000u) ? ~u : (u | 0x80000000u);
}
__device__ __forceinline__ float key_to_float(unsigned k) {
    unsigned u = (k & 0x80000000u) ? (k ^ 0x80000000u) : ~k;
    return __uint_as_float(u);
}

#define CAND_CAP 192
#define MARGIN 0.0075f

__global__ void __launch_bounds__(512)
fixup_kernel(float* __restrict__ P, const float* __restrict__ X,
             const float* __restrict__ Wm, float* __restrict__ out) {
    __shared__ float    s_row[N_DIM];
    __shared__ float    s_xs[K_DIM];
    __shared__ unsigned char s_mask[N_DIM];
    __shared__ unsigned hist[256];
    __shared__ unsigned s_wtot[8];
    __shared__ unsigned s_woff[8];
    __shared__ unsigned s_prefix, s_rem;
    __shared__ int      s_cnt, s_nc;
    __shared__ int      s_cidx[CAND_CAP];
    __shared__ float    s_cval[CAND_CAP];
    __shared__ float    s_wsum[16];
    __shared__ float    s_inv;

    const int row = blockIdx.x;
    const int tid = threadIdx.x;
    const int wid = tid >> 5, lane = tid & 31;
    const bool bip = (g_has_neg == 0);

    const float4* p4 = (const float4*)(P + (size_t)row * N_DIM);

    float v[8];
#pragma unroll
    for (int i = 0; i < 2; i++) {
        float4 f = p4[tid + 512 * i];
        const int cb = (tid + 512 * i) * 4;
        if (bip) {
            f.x = 2.f * f.x - g_S[cb + 0];
            f.y = 2.f * f.y - g_S[cb + 1];
            f.z = 2.f * f.z - g_S[cb + 2];
            f.w = 2.f * f.w - g_S[cb + 3];
        }
        v[i * 4 + 0] = f.x; v[i * 4 + 1] = f.y;
        v[i * 4 + 2] = f.z; v[i * 4 + 3] = f.w;
        s_row[cb + 0] = f.x; s_row[cb + 1] = f.y;
        s_row[cb + 2] = f.z; s_row[cb + 3] = f.w;
    }

    unsigned key[8];
#pragma unroll
    for (int i = 0; i < 8; i++) key[i] = float_to_key(v[i]);

    // load x row concurrently (independent of select)
#pragma unroll
    for (int i = 0; i < 2; i++) {
        const int k = tid + 512 * i;
        float xv = X[(size_t)row * K_DIM + k];
        s_xs[k] = bip ? (xv - 0.5f) * 2.0f : xv;
    }
    if (tid == 0) { s_cnt = 0; s_nc = 0; s_prefix = 0; s_rem = TOPK; }
    if (tid < 256) hist[tid] = 0;
    __syncthreads();

    // ---- 2-pass MSD radix select (top 16 key bits) ----
    unsigned prefix = 0;
    unsigned remaining = TOPK;
#pragma unroll
    for (int pass = 0; pass < 2; pass++) {
        const int shift = pass ? 16 : 24;
#pragma unroll
        for (int i = 0; i < 8; i++) {
            bool part = pass ? ((key[i] & 0xFF000000u) == prefix) : true;
            if (part) atomicAdd(&hist[(key[i] >> shift) & 255u], 1u);
        }
        __syncthreads();

        // phase 1: per-warp inclusive suffix scan (sfx stays in register)
        unsigned sfx = 0;
        if (tid < 256) {
            sfx = hist[tid];
#pragma unroll
            for (int off = 1; off < 32; off <<= 1) {
                unsigned u = __shfl_down_sync(0xFFFFFFFFu, sfx, off);
                if (lane + off < 32) sfx += u;
            }
            if (lane == 0) s_wtot[wid] = sfx;
        }
        __syncthreads();                       // all s_wtot visible

        // phase 2: warp-total suffix offsets
        if (tid < 8) {
            unsigned t2 = s_wtot[tid];
#pragma unroll
            for (int off = 1; off < 8; off <<= 1) {
                unsigned u = __shfl_down_sync(0xFFu, t2, off);
                if (tid + off < 8) t2 += u;
            }
            s_woff[tid] = t2 - s_wtot[tid];    // sum of warps strictly above
        }
        __syncthreads();                       // s_woff visible

        // phase 3: pick winner bin (suffix crossing)
        if (tid < 256) {
            const unsigned suffix = sfx + s_woff[wid];     // count(bins >= tid)
            unsigned nxt = __shfl_down_sync(0xFFFFFFFFu, suffix, 1);
            if (lane == 31) nxt = s_woff[wid];             // suffix of tid+1
            if (suffix >= remaining && nxt < remaining) {
                s_prefix = prefix | ((unsigned)tid << shift);
                s_rem = remaining - nxt;                   // rank inside bucket
            }
        }
        __syncthreads();
        prefix = s_prefix;
        remaining = s_rem;
        if (tid < 256) hist[tid] = 0;          // clear for next pass
        __syncthreads();
    }

    const float t_lo = key_to_float(prefix);
    const float t_hi = key_to_float(prefix | 0xFFFFu);
    const float hi = t_hi + MARGIN;
    const float lo = t_lo - MARGIN;

    // ---- candidates + sure count ----
    int myin = 0;
#pragma unroll
    for (int i = 0; i < 8; i++) {
        const int col = (tid + 512 * (i >> 2)) * 4 + (i & 3);
        const float val = v[i];
        const bool sure = (val > hi);
        s_mask[col] = sure ? 1 : 0;
        myin += sure ? 1 : 0;
        if (val <= hi && val >= lo) {
            int slot = atomicAdd(&s_nc, 1);
            if (slot < CAND_CAP) s_cidx[slot] = col;
        }
    }
#pragma unroll
    for (int off = 16; off >= 1; off >>= 1)
        myin += __shfl_xor_sync(0xFFFFFFFFu, myin, off);
    if (lane == 0) atomicAdd(&s_cnt, myin);
    __syncthreads();

    const int n_sure = s_cnt;
    const int n_c = min(s_nc, CAND_CAP);
    int need = TOPK - n_sure;
    if (need < 0) need = 0;
    if (need > n_c) need = n_c;

    // ---- exact fp32 dots for candidates (one warp per candidate) ----
    for (int j = wid; j < n_c; j += 16) {
        const int col = s_cidx[j];
        const float* wr = Wm + (size_t)col * K_DIM;
        float accv = 0.f;
#pragma unroll
        for (int i = 0; i < 32; i++) {
            const int k = lane + i * 32;
            accv = fmaf(s_xs[k], wr[k], accv);
        }
#pragma unroll
        for (int off = 16; off >= 1; off >>= 1)
            accv += __shfl_xor_sync(0xFFFFFFFFu, accv, off);
        if (lane == 0) {
            s_cval[j] = accv;
            s_row[col] = accv;
        }
    }
    __syncthreads();

    // ---- exact top-`need` among candidates ----
    if (tid < n_c) {
        const float vt = s_cval[tid];
        int rank = 0;
        for (int k = 0; k < n_c; k++) {
            const float vk = s_cval[k];
            rank += (vk > vt || (vk == vt && k < tid)) ? 1 : 0;
        }
        s_mask[s_cidx[tid]] = (rank < need) ? 1 : 0;
    }
    __syncthreads();

    // ---- encode + L2 normalize ----
    float e[8];
    float ss = 0.f;
#pragma unroll
    for (int i = 0; i < 8; i++) {
        const int col = (tid + 512 * (i >> 2)) * 4 + (i & 3);
        const float val = s_row[col];
        const float ev = s_mask[col] ? fmaxf(val, 0.f) : 0.f;
        e[i] = ev;
        ss = fmaf(ev, ev, ss);
    }
#pragma unroll
    for (int off = 16; off >= 1; off >>= 1)
        ss += __shfl_xor_sync(0xFFFFFFFFu, ss, off);
    if (lane == 0) s_wsum[wid] = ss;
    __syncthreads();
    if (tid == 0) {
        float tt = 0.f;
#pragma unroll
        for (int w = 0; w < 16; w++) tt += s_wsum[w];
        s_inv = 1.0f / fmaxf(sqrtf(tt), 1e-12f);
    }
    __syncthreads();
    const float inv = s_inv;

    float4* o4 = (float4*)(out + (size_t)row * N_DIM);
#pragma unroll
    for (int i = 0; i < 2; i++) {
        float4 f;
        f.x = e[i * 4 + 0] * inv; f.y = e[i * 4 + 1] * inv;
        f.z = e[i * 4 + 2] * inv; f.w = e[i * 4 + 3] * inv;
        o4[tid + 512 * i] = f;
    }
}

// ---------------------------------------------------------------------------
// Launch
// ---------------------------------------------------------------------------
extern "C" void kernel_launch(void* const* d_in, const int* in_sizes, int n_in,
                              void* d_out, int out_size) {
    const float* x = (const float*)d_in[0];   // [16384, 1024]
    const float* w = (const float*)d_in[1];   // [4096, 1024]
    float* out = (float*)d_out;               // [16384, 4096]

    const int smem_bytes = NSTAGES * STAGE_B;
    cudaFuncSetAttribute(gemm_f16_kernel,
                         cudaFuncAttributeMaxDynamicSharedMemorySize, smem_bytes);

    init_flags_kernel<<<1, 1>>>();
    conv_x_scan_kernel<<<2048, 256>>>((const float4*)x);
    conv_w_rowsum_kernel<<<N_DIM, 256>>>((const float4*)w);

    dim3 ggrid(N_DIM / 128, M_DIM / 128);
    gemm_f16_kernel<<<ggrid, 256, smem_bytes>>>(out);

    fixup_kernel<<<M_DIM, 512>>>(out, x, w, out);
}